// round 2
// baseline (speedup 1.0000x reference)
#include <cuda_runtime.h>
#include <math.h>

#define Bsz  4
#define Msz  256
#define Tsz  64
#define BT   256          // B*T
#define DMOT 512
#define DOUT 768

// Scratch (allocation-free rule: __device__ globals)
__device__ float g_Ubig[768 * DMOT];     // rows r = bt*3+comp: comp0->u1 interleaved even, comp1->u1 odd, comp2->(vis*cx, vis*cy)
__device__ float g_Wstack[769 * DMOT];   // rows 0..767 = Ubig@fc1_w ; row 768 = fc1_b
__device__ float g_ABC[769 * DOUT];      // rows (bt*3+comp) = A,B,C ; row 768 = fc1_b@Wout_top (Bias1)
__device__ float g_pb[Msz * DOUT];       // pos@Wout_bot + fc_out_b + Bias1

// ---------------------------------------------------------------------------
// K1: build Ubig from coords/vis (with NaN masking) + copy fc1_b into Wstack row 768
// ---------------------------------------------------------------------------
__global__ void build_u_kernel(const float* __restrict__ coord,
                               const float* __restrict__ vism,
                               const float* __restrict__ fc1b) {
    int idx = blockIdx.x * blockDim.x + threadIdx.x;
    if (idx < BT * Msz) {
        int n  = idx & (Msz - 1);
        int bt = idx >> 8;
        int b  = bt >> 6;
        int t  = bt & (Tsz - 1);
        int ci = (b * Msz + n) * Tsz + t;
        float cx = coord[2 * ci + 0];
        float cy = coord[2 * ci + 1];
        float v  = vism[ci];
        float cxp = isnan(cx) ? 0.f : cx;
        float cyp = isnan(cy) ? 0.f : cy;
        float vp  = isnan(cx) ? 0.f : v;
        int r0 = bt * 3 * DMOT;
        g_Ubig[r0 + 2 * n    ]          = vp;
        g_Ubig[r0 + 2 * n + 1]          = 0.f;
        g_Ubig[r0 + DMOT + 2 * n    ]   = 0.f;
        g_Ubig[r0 + DMOT + 2 * n + 1]   = vp;
        g_Ubig[r0 + 2 * DMOT + 2 * n  ] = vp * cxp;
        g_Ubig[r0 + 2 * DMOT + 2 * n + 1] = vp * cyp;
    }
    if (idx < DMOT) g_Wstack[768 * DMOT + idx] = fc1b[idx];
}

// ---------------------------------------------------------------------------
// Generic fp32 tiled GEMM: C[M,N] = A[M,K] @ B[K,N] (+ bias0[col] + bias1[col])
// 64x64 tile, BK=16, 256 threads, 4x4 per thread. K must be multiple of 16,
// N and K-tiles in-bounds; only M may be ragged (guarded).
// ---------------------------------------------------------------------------
__global__ void gemm64x64(int M, int N, int K,
                          const float* __restrict__ A,
                          const float* __restrict__ Bm,
                          float* __restrict__ C,
                          const float* __restrict__ bias0,
                          const float* __restrict__ bias1) {
    __shared__ float As[16][64];
    __shared__ float Bs[16][64];
    const int bm = blockIdx.y * 64, bn = blockIdx.x * 64;
    const int tid = threadIdx.x;
    const int tr = tid >> 4;          // 0..15
    const int tc = tid & 15;          // 0..15
    const int am  = tid >> 2;         // 0..63
    const int akq = (tid & 3) * 4;    // 0,4,8,12
    const int bk  = tid >> 4;         // 0..15
    const int bnq = (tid & 15) * 4;   // 0..60
    const int arow = bm + am;
    float acc[4][4] = {};

    for (int k0 = 0; k0 < K; k0 += 16) {
        float4 av = make_float4(0.f, 0.f, 0.f, 0.f);
        if (arow < M)
            av = *reinterpret_cast<const float4*>(&A[(size_t)arow * K + k0 + akq]);
        float4 bv = *reinterpret_cast<const float4*>(&Bm[(size_t)(k0 + bk) * N + bn + bnq]);
        As[akq + 0][am] = av.x;
        As[akq + 1][am] = av.y;
        As[akq + 2][am] = av.z;
        As[akq + 3][am] = av.w;
        *reinterpret_cast<float4*>(&Bs[bk][bnq]) = bv;
        __syncthreads();
#pragma unroll
        for (int kk = 0; kk < 16; kk++) {
            float4 a4 = *reinterpret_cast<const float4*>(&As[kk][tr * 4]);
            float4 b4 = *reinterpret_cast<const float4*>(&Bs[kk][tc * 4]);
            acc[0][0] += a4.x * b4.x; acc[0][1] += a4.x * b4.y; acc[0][2] += a4.x * b4.z; acc[0][3] += a4.x * b4.w;
            acc[1][0] += a4.y * b4.x; acc[1][1] += a4.y * b4.y; acc[1][2] += a4.y * b4.z; acc[1][3] += a4.y * b4.w;
            acc[2][0] += a4.z * b4.x; acc[2][1] += a4.z * b4.y; acc[2][2] += a4.z * b4.z; acc[2][3] += a4.z * b4.w;
            acc[3][0] += a4.w * b4.x; acc[3][1] += a4.w * b4.y; acc[3][2] += a4.w * b4.z; acc[3][3] += a4.w * b4.w;
        }
        __syncthreads();
    }

    float bb[4] = {0.f, 0.f, 0.f, 0.f};
#pragma unroll
    for (int j = 0; j < 4; j++) {
        int col = bn + tc * 4 + j;
        if (bias0) bb[j] += bias0[col];
        if (bias1) bb[j] += bias1[col];
    }
#pragma unroll
    for (int i = 0; i < 4; i++) {
        int row = bm + tr * 4 + i;
        if (row < M) {
#pragma unroll
            for (int j = 0; j < 4; j++)
                C[(size_t)row * N + bn + tc * 4 + j] = acc[i][j] + bb[j];
        }
    }
}

// ---------------------------------------------------------------------------
// K5: streaming epilogue — out[bt,m,o] = vis*(cx*A + cy*B - C) + pb[m,o]
// grid (BT, 8) x 192 threads ; each thread owns a float4 of o, loops 32 m's.
// ---------------------------------------------------------------------------
__global__ void epilogue_kernel(const float* __restrict__ coord,
                                const float* __restrict__ vism,
                                float* __restrict__ out) {
    const int bt = blockIdx.x;
    const int m0 = blockIdx.y * 32;
    const int o  = threadIdx.x * 4;
    const int b  = bt >> 6;
    const int t  = bt & 63;
    const float4 A4 = *reinterpret_cast<const float4*>(&g_ABC[(bt * 3 + 0) * DOUT + o]);
    const float4 B4 = *reinterpret_cast<const float4*>(&g_ABC[(bt * 3 + 1) * DOUT + o]);
    const float4 C4 = *reinterpret_cast<const float4*>(&g_ABC[(bt * 3 + 2) * DOUT + o]);
#pragma unroll 4
    for (int mm = 0; mm < 32; mm++) {
        int m  = m0 + mm;
        int ci = (b * Msz + m) * Tsz + t;
        float cx = coord[2 * ci + 0];
        float cy = coord[2 * ci + 1];
        float v  = vism[ci];
        float cxp = isnan(cx) ? 0.f : cx;
        float cyp = isnan(cy) ? 0.f : cy;
        float vp  = isnan(cx) ? 0.f : v;
        float4 p4 = *reinterpret_cast<const float4*>(&g_pb[m * DOUT + o]);
        float4 r;
        r.x = vp * (cxp * A4.x + cyp * B4.x - C4.x) + p4.x;
        r.y = vp * (cxp * A4.y + cyp * B4.y - C4.y) + p4.y;
        r.z = vp * (cxp * A4.z + cyp * B4.z - C4.z) + p4.z;
        r.w = vp * (cxp * A4.w + cyp * B4.w - C4.w) + p4.w;
        *reinterpret_cast<float4*>(&out[((size_t)bt * Msz + m) * DOUT + o]) = r;
    }
}

// ---------------------------------------------------------------------------
extern "C" void kernel_launch(void* const* d_in, const int* in_sizes, int n_in,
                              void* d_out, int out_size) {
    const float* coord = (const float*)d_in[0];
    const float* vism  = (const float*)d_in[1];
    const float* pos   = (const float*)d_in[2];
    const float* fc1w  = (const float*)d_in[3];
    const float* fc1b  = (const float*)d_in[4];
    const float* fow   = (const float*)d_in[5];
    const float* fob   = (const float*)d_in[6];
    float* out = (float*)d_out;

    float *Ubig, *Wstack, *ABC, *pb;
    cudaGetSymbolAddress((void**)&Ubig,   g_Ubig);
    cudaGetSymbolAddress((void**)&Wstack, g_Wstack);
    cudaGetSymbolAddress((void**)&ABC,    g_ABC);
    cudaGetSymbolAddress((void**)&pb,     g_pb);

    // K1: build masked u-vectors (Ubig) + fc1_b row
    build_u_kernel<<<(BT * Msz) / 256, 256>>>(coord, vism, fc1b);

    // GEMM1: Wstack[0..767] = Ubig(768x512) @ fc1_w(512x512)
    gemm64x64<<<dim3(DMOT / 64, 768 / 64), 256>>>(768, DMOT, DMOT,
                                                  Ubig, fc1w, Wstack, nullptr, nullptr);

    // GEMM2: ABC(769x768) = Wstack(769x512) @ fc_out_w[:512](512x768)
    gemm64x64<<<dim3(DOUT / 64, 13), 256>>>(769, DOUT, DMOT,
                                            Wstack, fow, ABC, nullptr, nullptr);

    // GEMM3: pb(256x768) = pos(256x512) @ fc_out_w[512:](512x768) + fc_out_b + Bias1(=ABC row 768)
    gemm64x64<<<dim3(DOUT / 64, Msz / 64), 256>>>(Msz, DOUT, DMOT,
                                                  pos, fow + (size_t)512 * DOUT, pb,
                                                  fob, ABC + (size_t)768 * DOUT);

    // K5: fused epilogue, writes all 50.3M outputs
    epilogue_kernel<<<dim3(BT, 8), 192>>>(coord, vism, out);
}

// round 4
// speedup vs baseline: 1.8438x; 1.8438x over previous
#include <cuda_runtime.h>
#include <cuda_bf16.h>
#include <cstdint>
#include <math.h>

#define Bsz  4
#define Msz  256
#define Tsz  64
#define BT   256          // B*T
#define DMOT 512
#define DOUT 768
#define GK   512          // K dim of all GEMMs

// ---------------------------------------------------------------------------
// Scratch (__device__ globals — allocation-free rule)
// ---------------------------------------------------------------------------
__device__ __nv_bfloat16 g_Ub_h[768 * GK], g_Ub_l[768 * GK];      // A of GEMM1
__device__ __nv_bfloat16 g_Ws_h[769 * GK], g_Ws_l[769 * GK];      // A of GEMM2 (GEMM1 out + fc1_b row)
__device__ __nv_bfloat16 g_W1_h[512 * GK], g_W1_l[512 * GK];      // fc1_w^T   [512n][512k]
__device__ __nv_bfloat16 g_W2_h[768 * GK], g_W2_l[768 * GK];      // fow_top^T [768n][512k]
__device__ __nv_bfloat16 g_W3_h[768 * GK], g_W3_l[768 * GK];      // fow_bot^T [768n][512k]
__device__ __nv_bfloat16 g_ps_h[256 * GK], g_ps_l[256 * GK];      // pos split
__device__ float g_ABC[769 * DOUT];                               // A,B,C rows + Bias1 row 768
__device__ float g_pb[Msz * DOUT];                                // pos@Wbot + fob + Bias1

__device__ __forceinline__ void split_store(float v, __nv_bfloat16* h, __nv_bfloat16* l, size_t o) {
    __nv_bfloat16 hh = __float2bfloat16(v);
    h[o] = hh;
    l[o] = __float2bfloat16(v - __bfloat162float(hh));
}

// ---------------------------------------------------------------------------
// K1: build Ubig (bf16 hi/lo) from coords/vis + fc1_b into Wstack row 768
// ---------------------------------------------------------------------------
__global__ void build_u_kernel(const float* __restrict__ coord,
                               const float* __restrict__ vism,
                               const float* __restrict__ fc1b) {
    int idx = blockIdx.x * blockDim.x + threadIdx.x;
    if (idx < BT * Msz) {
        int n  = idx & (Msz - 1);
        int bt = idx >> 8;
        int b  = bt >> 6;
        int t  = bt & (Tsz - 1);
        int ci = (b * Msz + n) * Tsz + t;
        float cx = coord[2 * ci + 0];
        float cy = coord[2 * ci + 1];
        float v  = vism[ci];
        float cxp = isnan(cx) ? 0.f : cx;
        float cyp = isnan(cy) ? 0.f : cy;
        float vp  = isnan(cx) ? 0.f : v;
        size_t r0 = (size_t)bt * 3 * GK;
        __nv_bfloat16 z = __float2bfloat16(0.f);
        split_store(vp, g_Ub_h, g_Ub_l, r0 + 2 * n);
        g_Ub_h[r0 + 2 * n + 1] = z;  g_Ub_l[r0 + 2 * n + 1] = z;
        g_Ub_h[r0 + GK + 2 * n] = z; g_Ub_l[r0 + GK + 2 * n] = z;
        split_store(vp,        g_Ub_h, g_Ub_l, r0 + GK + 2 * n + 1);
        split_store(vp * cxp,  g_Ub_h, g_Ub_l, r0 + 2 * GK + 2 * n);
        split_store(vp * cyp,  g_Ub_h, g_Ub_l, r0 + 2 * GK + 2 * n + 1);
    }
    if (idx < DMOT) split_store(fc1b[idx], g_Ws_h, g_Ws_l, (size_t)768 * GK + idx);
}

// ---------------------------------------------------------------------------
// K2: generic fp32 -> bf16 hi/lo split (for pos)
// ---------------------------------------------------------------------------
__global__ void split_kernel(const float* __restrict__ src,
                             __nv_bfloat16* __restrict__ h,
                             __nv_bfloat16* __restrict__ l, int n) {
    int i = blockIdx.x * blockDim.x + threadIdx.x;
    if (i < n) split_store(src[i], h, l, i);
}

// ---------------------------------------------------------------------------
// K3: transpose+split: W[K x N] (row stride ldw) -> T[N x K] bf16 hi/lo
// ---------------------------------------------------------------------------
__global__ void transpose_split(const float* __restrict__ W, int ldw, int Kdim,
                                __nv_bfloat16* __restrict__ Th,
                                __nv_bfloat16* __restrict__ Tl) {
    __shared__ float t[32][33];
    int n0 = blockIdx.x * 32, k0 = blockIdx.y * 32;
    int tx = threadIdx.x, ty = threadIdx.y;
#pragma unroll
    for (int i = 0; i < 4; i++)
        t[ty + i * 8][tx] = W[(size_t)(k0 + ty + i * 8) * ldw + n0 + tx];
    __syncthreads();
#pragma unroll
    for (int i = 0; i < 4; i++) {
        float v = t[tx][ty + i * 8];
        split_store(v, Th, Tl, (size_t)(n0 + ty + i * 8) * Kdim + k0 + tx);
    }
}

// ---------------------------------------------------------------------------
// K4: bf16 mma.sync GEMM with 3-term hi/lo split.
// CTA 128(M) x 64(N), 256 threads = 8 warps (4x2), warp tile 32x32.
// A[M x 512] K-major hi/lo, B[N x 512] K-major hi/lo. K chunks of 32, double buffer.
// SMEM rows padded to 40 bf16 (80B) -> conflict-free 32-bit fragment loads.
// ---------------------------------------------------------------------------
#define CH   32
#define AST  40   // A smem row stride (bf16)
#define BST  40
#define A_ELE (128 * AST)   // 5120 per buffer
#define B_ELE (64 * BST)    // 2560 per buffer
#define GEMM_SMEM ((2 * A_ELE * 2 + 2 * B_ELE * 2) * 2)  // 61440 bytes

__device__ __forceinline__ void mma16816(float* c, const uint32_t* a, const uint32_t* b) {
    asm volatile(
        "mma.sync.aligned.m16n8k16.row.col.f32.bf16.bf16.f32 "
        "{%0,%1,%2,%3}, {%4,%5,%6,%7}, {%8,%9}, {%0,%1,%2,%3};\n"
        : "+f"(c[0]), "+f"(c[1]), "+f"(c[2]), "+f"(c[3])
        : "r"(a[0]), "r"(a[1]), "r"(a[2]), "r"(a[3]), "r"(b[0]), "r"(b[1]));
}

__global__ __launch_bounds__(256, 1) void gemm_mma(
    int M, int N,
    const __nv_bfloat16* __restrict__ Ah, const __nv_bfloat16* __restrict__ Al,
    const __nv_bfloat16* __restrict__ Bh, const __nv_bfloat16* __restrict__ Bl,
    float* __restrict__ Cf,
    __nv_bfloat16* __restrict__ Ch, __nv_bfloat16* __restrict__ Cl,
    const float* __restrict__ bias0, const float* __restrict__ bias1) {
    extern __shared__ __nv_bfloat16 sm[];
    __nv_bfloat16* sAh = sm;                       // [2][128][40]
    __nv_bfloat16* sAl = sm + 2 * A_ELE;
    __nv_bfloat16* sBh = sm + 4 * A_ELE;           // [2][64][40]
    __nv_bfloat16* sBl = sm + 4 * A_ELE + 2 * B_ELE;

    const int tid  = threadIdx.x;
    const int wid  = tid >> 5, lane = tid & 31;
    const int bm = blockIdx.y * 128, bn = blockIdx.x * 64;
    const int wm = (wid >> 1) * 32, wn = (wid & 1) * 32;

    // load assignments
    const int ar = tid >> 1;            // A row 0..127
    const int as0 = (tid & 1);          // segs as0, as0+2 (8 bf16 each)
    const int br = tid >> 2;            // B row 0..63
    const int bs = (tid & 3);           // seg

    const int arow = bm + ar;
    const bool aok = arow < M;
    const uint4 z4 = make_uint4(0, 0, 0, 0);

    float acc[2][4][4] = {};
    uint4 rah0, rah1, ral0, ral1, rbh, rbl;

    auto gload = [&](int c) {
        const uint4* pah = reinterpret_cast<const uint4*>(Ah + (size_t)arow * GK + c * CH);
        const uint4* pal = reinterpret_cast<const uint4*>(Al + (size_t)arow * GK + c * CH);
        rah0 = aok ? pah[as0]     : z4;
        rah1 = aok ? pah[as0 + 2] : z4;
        ral0 = aok ? pal[as0]     : z4;
        ral1 = aok ? pal[as0 + 2] : z4;
        const uint4* pbh = reinterpret_cast<const uint4*>(Bh + (size_t)(bn + br) * GK + c * CH);
        const uint4* pbl = reinterpret_cast<const uint4*>(Bl + (size_t)(bn + br) * GK + c * CH);
        rbh = pbh[bs];
        rbl = pbl[bs];
    };
    auto sstore = [&](int buf) {
        __nv_bfloat16* dAh = sAh + buf * A_ELE + ar * AST;
        __nv_bfloat16* dAl = sAl + buf * A_ELE + ar * AST;
        *reinterpret_cast<uint4*>(dAh + as0 * 8)       = rah0;
        *reinterpret_cast<uint4*>(dAh + (as0 + 2) * 8) = rah1;
        *reinterpret_cast<uint4*>(dAl + as0 * 8)       = ral0;
        *reinterpret_cast<uint4*>(dAl + (as0 + 2) * 8) = ral1;
        *reinterpret_cast<uint4*>(sBh + buf * B_ELE + br * BST + bs * 8) = rbh;
        *reinterpret_cast<uint4*>(sBl + buf * B_ELE + br * BST + bs * 8) = rbl;
    };

    gload(0);
    sstore(0);
    __syncthreads();

    const int g   = lane >> 2;          // 0..7
    const int kq  = (lane & 3) * 2;     // 0,2,4,6

    for (int c = 0; c < GK / CH; c++) {
        const int buf = c & 1;
        if (c + 1 < GK / CH) gload(c + 1);

        const __nv_bfloat16* bAh = sAh + buf * A_ELE;
        const __nv_bfloat16* bAl = sAl + buf * A_ELE;
        const __nv_bfloat16* bBh = sBh + buf * B_ELE;
        const __nv_bfloat16* bBl = sBl + buf * B_ELE;
#pragma unroll
        for (int ks = 0; ks < 2; ks++) {
            const int k0 = ks * 16 + kq;
            uint32_t fah[2][4], fal[2][4], fbh[4][2], fbl[4][2];
#pragma unroll
            for (int mt = 0; mt < 2; mt++) {
                const int r0 = wm + mt * 16 + g;
                fah[mt][0] = *reinterpret_cast<const uint32_t*>(bAh + r0 * AST + k0);
                fah[mt][1] = *reinterpret_cast<const uint32_t*>(bAh + (r0 + 8) * AST + k0);
                fah[mt][2] = *reinterpret_cast<const uint32_t*>(bAh + r0 * AST + k0 + 8);
                fah[mt][3] = *reinterpret_cast<const uint32_t*>(bAh + (r0 + 8) * AST + k0 + 8);
                fal[mt][0] = *reinterpret_cast<const uint32_t*>(bAl + r0 * AST + k0);
                fal[mt][1] = *reinterpret_cast<const uint32_t*>(bAl + (r0 + 8) * AST + k0);
                fal[mt][2] = *reinterpret_cast<const uint32_t*>(bAl + r0 * AST + k0 + 8);
                fal[mt][3] = *reinterpret_cast<const uint32_t*>(bAl + (r0 + 8) * AST + k0 + 8);
            }
#pragma unroll
            for (int nt = 0; nt < 4; nt++) {
                const int cn = wn + nt * 8 + g;
                fbh[nt][0] = *reinterpret_cast<const uint32_t*>(bBh + cn * BST + k0);
                fbh[nt][1] = *reinterpret_cast<const uint32_t*>(bBh + cn * BST + k0 + 8);
                fbl[nt][0] = *reinterpret_cast<const uint32_t*>(bBl + cn * BST + k0);
                fbl[nt][1] = *reinterpret_cast<const uint32_t*>(bBl + cn * BST + k0 + 8);
            }
#pragma unroll
            for (int mt = 0; mt < 2; mt++)
#pragma unroll
                for (int nt = 0; nt < 4; nt++) {
                    mma16816(acc[mt][nt], fah[mt], fbh[nt]);
                    mma16816(acc[mt][nt], fah[mt], fbl[nt]);
                    mma16816(acc[mt][nt], fal[mt], fbh[nt]);
                }
        }
        if (c + 1 < GK / CH) sstore(buf ^ 1);
        __syncthreads();
    }

    // write out: c0:(r0,c0) c1:(r0,c0+1) c2:(r0+8,c0) c3:(r0+8,c0+1)
#pragma unroll
    for (int mt = 0; mt < 2; mt++) {
        const int r0 = bm + wm + mt * 16 + g;
#pragma unroll
        for (int nt = 0; nt < 4; nt++) {
            const int c0 = bn + wn + nt * 8 + kq;
#pragma unroll
            for (int half = 0; half < 2; half++) {
                const int row = r0 + half * 8;
                if (row < M) {
                    float v0 = acc[mt][nt][half * 2 + 0];
                    float v1 = acc[mt][nt][half * 2 + 1];
                    if (bias0) { v0 += bias0[c0]; v1 += bias0[c0 + 1]; }
                    if (bias1) { v0 += bias1[c0]; v1 += bias1[c0 + 1]; }
                    size_t o = (size_t)row * N + c0;
                    if (Ch) {
                        split_store(v0, Ch, Cl, o);
                        split_store(v1, Ch, Cl, o + 1);
                    } else {
                        Cf[o] = v0;
                        Cf[o + 1] = v1;
                    }
                }
            }
        }
    }
}

// ---------------------------------------------------------------------------
// K5: epilogue. Block = (32 m) x (16 bt), pb tile cached in SMEM.
// out[bt,m,o] = vp*(cx*A[bt,o] + cy*B[bt,o] - C[bt,o]) + pb[m,o]
// ---------------------------------------------------------------------------
__global__ __launch_bounds__(192, 1) void epilogue_kernel(
    const float* __restrict__ coord,
    const float* __restrict__ vism,
    float* __restrict__ out) {
    extern __shared__ float smf[];
    float4* pbs = reinterpret_cast<float4*>(smf);                   // [32][192] float4
    float4* cc  = reinterpret_cast<float4*>(smf + 32 * DOUT);       // [16*32] (cx,cy,vp,_)
    const int m0  = blockIdx.x * 32;
    const int bt0 = blockIdx.y * 16;
    const int tid = threadIdx.x;

    const float4* pb4 = reinterpret_cast<const float4*>(g_pb);
    for (int i = tid; i < 32 * 192; i += 192) {
        int r = i / 192, cf = i % 192;
        pbs[i] = pb4[(size_t)(m0 + r) * 192 + cf];
    }
    for (int e = tid; e < 512; e += 192) {
        int btl = e >> 5, ml = e & 31;
        int bt = bt0 + btl, m = m0 + ml;
        int b = bt >> 6, t = bt & 63;
        int ci = (b * Msz + m) * Tsz + t;
        float cx = coord[2 * ci + 0];
        float cy = coord[2 * ci + 1];
        float v  = vism[ci];
        float cxp = isnan(cx) ? 0.f : cx;
        float cyp = isnan(cy) ? 0.f : cy;
        float vp  = isnan(cx) ? 0.f : v;
        cc[e] = make_float4(cxp, cyp, vp, 0.f);
    }
    __syncthreads();

    const int o = tid * 4;
    for (int btl = 0; btl < 16; btl++) {
        const int bt = bt0 + btl;
        const float4 A4 = *reinterpret_cast<const float4*>(&g_ABC[(size_t)(bt * 3 + 0) * DOUT + o]);
        const float4 B4 = *reinterpret_cast<const float4*>(&g_ABC[(size_t)(bt * 3 + 1) * DOUT + o]);
        const float4 C4 = *reinterpret_cast<const float4*>(&g_ABC[(size_t)(bt * 3 + 2) * DOUT + o]);
        float* obase = out + ((size_t)bt * Msz + m0) * DOUT + o;
#pragma unroll 4
        for (int ml = 0; ml < 32; ml++) {
            float4 k = cc[btl * 32 + ml];
            float4 p = pbs[ml * 192 + tid];
            float4 r;
            r.x = k.z * (k.x * A4.x + k.y * B4.x - C4.x) + p.x;
            r.y = k.z * (k.x * A4.y + k.y * B4.y - C4.y) + p.y;
            r.z = k.z * (k.x * A4.z + k.y * B4.z - C4.z) + p.z;
            r.w = k.z * (k.x * A4.w + k.y * B4.w - C4.w) + p.w;
            *reinterpret_cast<float4*>(obase + (size_t)ml * DOUT) = r;
        }
    }
}

// ---------------------------------------------------------------------------
extern "C" void kernel_launch(void* const* d_in, const int* in_sizes, int n_in,
                              void* d_out, int out_size) {
    const float* coord = (const float*)d_in[0];
    const float* vism  = (const float*)d_in[1];
    const float* pos   = (const float*)d_in[2];
    const float* fc1w  = (const float*)d_in[3];
    const float* fc1b  = (const float*)d_in[4];
    const float* fow   = (const float*)d_in[5];
    const float* fob   = (const float*)d_in[6];
    float* out = (float*)d_out;

    __nv_bfloat16 *Ubh, *Ubl, *Wsh, *Wsl, *W1h, *W1l, *W2h, *W2l, *W3h, *W3l, *psh, *psl;
    float *ABC, *pb;
    cudaGetSymbolAddress((void**)&Ubh, g_Ub_h); cudaGetSymbolAddress((void**)&Ubl, g_Ub_l);
    cudaGetSymbolAddress((void**)&Wsh, g_Ws_h); cudaGetSymbolAddress((void**)&Wsl, g_Ws_l);
    cudaGetSymbolAddress((void**)&W1h, g_W1_h); cudaGetSymbolAddress((void**)&W1l, g_W1_l);
    cudaGetSymbolAddress((void**)&W2h, g_W2_h); cudaGetSymbolAddress((void**)&W2l, g_W2_l);
    cudaGetSymbolAddress((void**)&W3h, g_W3_h); cudaGetSymbolAddress((void**)&W3l, g_W3_l);
    cudaGetSymbolAddress((void**)&psh, g_ps_h); cudaGetSymbolAddress((void**)&psl, g_ps_l);
    cudaGetSymbolAddress((void**)&ABC, g_ABC);  cudaGetSymbolAddress((void**)&pb,  g_pb);

    cudaFuncSetAttribute(gemm_mma, cudaFuncAttributeMaxDynamicSharedMemorySize, GEMM_SMEM);
    cudaFuncSetAttribute(epilogue_kernel, cudaFuncAttributeMaxDynamicSharedMemorySize,
                         32 * DOUT * 4 + 512 * 16);

    // prep: masked u-vectors, pos split, weight transposes+splits
    build_u_kernel<<<BT * Msz / 256, 256>>>(coord, vism, fc1b);
    split_kernel<<<(Msz * GK) / 256, 256>>>(pos, psh, psl, Msz * GK);
    transpose_split<<<dim3(512 / 32, GK / 32), dim3(32, 8)>>>(fc1w, 512, GK, W1h, W1l);
    transpose_split<<<dim3(DOUT / 32, GK / 32), dim3(32, 8)>>>(fow, DOUT, GK, W2h, W2l);
    transpose_split<<<dim3(DOUT / 32, GK / 32), dim3(32, 8)>>>(fow + (size_t)512 * DOUT, DOUT, GK, W3h, W3l);

    // GEMM1: Wstack[0..767] = Ub(768x512) @ fc1_w  -> bf16 split out
    gemm_mma<<<dim3(DMOT / 64, 6), 256, GEMM_SMEM>>>(768, DMOT, Ubh, Ubl, W1h, W1l,
                                                     nullptr, Wsh, Wsl, nullptr, nullptr);
    // GEMM2: ABC(769x768) = Wstack(769x512) @ fow_top -> fp32
    gemm_mma<<<dim3(DOUT / 64, 7), 256, GEMM_SMEM>>>(769, DOUT, Wsh, Wsl, W2h, W2l,
                                                     ABC, nullptr, nullptr, nullptr, nullptr);
    // GEMM3: pb(256x768) = pos @ fow_bot + fob + Bias1(ABC row 768) -> fp32
    gemm_mma<<<dim3(DOUT / 64, 2), 256, GEMM_SMEM>>>(Msz, DOUT, psh, psl, W3h, W3l,
                                                     pb, nullptr, nullptr, fob, ABC + (size_t)768 * DOUT);

    // epilogue: stream 201MB output
    epilogue_kernel<<<dim3(Msz / 32, BT / 16), 192, 32 * DOUT * 4 + 512 * 16>>>(coord, vism, out);
}

// round 5
// speedup vs baseline: 1.9503x; 1.0578x over previous
#include <cuda_runtime.h>
#include <cuda_bf16.h>
#include <cstdint>
#include <math.h>

#define Bsz  4
#define Msz  256
#define Tsz  64
#define BT   256          // B*T
#define DMOT 512
#define DOUT 768
#define GK   512          // K dim of all GEMMs

// ---------------------------------------------------------------------------
// Scratch (__device__ globals — allocation-free rule)
// ---------------------------------------------------------------------------
__device__ __nv_bfloat16 g_Ub_h[768 * GK], g_Ub_l[768 * GK];      // A of GEMM1
__device__ __nv_bfloat16 g_Ws_h[769 * GK], g_Ws_l[769 * GK];      // A of GEMM2 (GEMM1 out + fc1_b row)
__device__ __nv_bfloat16 g_W1_h[512 * GK], g_W1_l[512 * GK];      // fc1_w^T   [512n][512k]
__device__ __nv_bfloat16 g_W2_h[768 * GK], g_W2_l[768 * GK];      // fow_top^T [768n][512k]
__device__ __nv_bfloat16 g_W3_h[768 * GK], g_W3_l[768 * GK];      // fow_bot^T [768n][512k]
__device__ __nv_bfloat16 g_ps_h[256 * GK], g_ps_l[256 * GK];      // pos split
__device__ float g_ABC[769 * DOUT];                               // A,B,C rows + Bias1 row 768
__device__ float g_pb[Msz * DOUT];                                // pos@Wbot + fob + Bias1

__device__ __forceinline__ void split_store(float v, __nv_bfloat16* h, __nv_bfloat16* l, size_t o) {
    __nv_bfloat16 hh = __float2bfloat16(v);
    h[o] = hh;
    l[o] = __float2bfloat16(v - __bfloat162float(hh));
}

// ---------------------------------------------------------------------------
// K1: build Ubig (bf16 hi/lo) from coords/vis + fc1_b into Wstack row 768
// ---------------------------------------------------------------------------
__global__ void build_u_kernel(const float* __restrict__ coord,
                               const float* __restrict__ vism,
                               const float* __restrict__ fc1b) {
    int idx = blockIdx.x * blockDim.x + threadIdx.x;
    if (idx < BT * Msz) {
        int n  = idx & (Msz - 1);
        int bt = idx >> 8;
        int b  = bt >> 6;
        int t  = bt & (Tsz - 1);
        int ci = (b * Msz + n) * Tsz + t;
        float cx = coord[2 * ci + 0];
        float cy = coord[2 * ci + 1];
        float v  = vism[ci];
        float cxp = isnan(cx) ? 0.f : cx;
        float cyp = isnan(cy) ? 0.f : cy;
        float vp  = isnan(cx) ? 0.f : v;
        size_t r0 = (size_t)bt * 3 * GK;
        __nv_bfloat16 z = __float2bfloat16(0.f);
        split_store(vp, g_Ub_h, g_Ub_l, r0 + 2 * n);
        g_Ub_h[r0 + 2 * n + 1] = z;  g_Ub_l[r0 + 2 * n + 1] = z;
        g_Ub_h[r0 + GK + 2 * n] = z; g_Ub_l[r0 + GK + 2 * n] = z;
        split_store(vp,        g_Ub_h, g_Ub_l, r0 + GK + 2 * n + 1);
        split_store(vp * cxp,  g_Ub_h, g_Ub_l, r0 + 2 * GK + 2 * n);
        split_store(vp * cyp,  g_Ub_h, g_Ub_l, r0 + 2 * GK + 2 * n + 1);
    }
    if (idx < DMOT) split_store(fc1b[idx], g_Ws_h, g_Ws_l, (size_t)768 * GK + idx);
}

// ---------------------------------------------------------------------------
// K2: generic fp32 -> bf16 hi/lo split (for pos)
// ---------------------------------------------------------------------------
__global__ void split_kernel(const float* __restrict__ src,
                             __nv_bfloat16* __restrict__ h,
                             __nv_bfloat16* __restrict__ l, int n) {
    int i = blockIdx.x * blockDim.x + threadIdx.x;
    if (i < n) split_store(src[i], h, l, i);
}

// ---------------------------------------------------------------------------
// K3: transpose+split: W[K x N] (row stride ldw) -> T[N x K] bf16 hi/lo
// ---------------------------------------------------------------------------
__global__ void transpose_split(const float* __restrict__ W, int ldw, int Kdim,
                                __nv_bfloat16* __restrict__ Th,
                                __nv_bfloat16* __restrict__ Tl) {
    __shared__ float t[32][33];
    int n0 = blockIdx.x * 32, k0 = blockIdx.y * 32;
    int tx = threadIdx.x, ty = threadIdx.y;
#pragma unroll
    for (int i = 0; i < 4; i++)
        t[ty + i * 8][tx] = W[(size_t)(k0 + ty + i * 8) * ldw + n0 + tx];
    __syncthreads();
#pragma unroll
    for (int i = 0; i < 4; i++) {
        float v = t[tx][ty + i * 8];
        split_store(v, Th, Tl, (size_t)(n0 + ty + i * 8) * Kdim + k0 + tx);
    }
}

// ---------------------------------------------------------------------------
// K4: bf16 mma.sync GEMM with 3-term hi/lo split.
// CTA 128(M) x 64(N), 256 threads = 8 warps (4x2), warp tile 32x32.
// ---------------------------------------------------------------------------
#define CH   32
#define AST  40
#define BST  40
#define A_ELE (128 * AST)
#define B_ELE (64 * BST)
#define GEMM_SMEM ((2 * A_ELE * 2 + 2 * B_ELE * 2) * 2)  // 61440 bytes

__device__ __forceinline__ void mma16816(float* c, const uint32_t* a, const uint32_t* b) {
    asm volatile(
        "mma.sync.aligned.m16n8k16.row.col.f32.bf16.bf16.f32 "
        "{%0,%1,%2,%3}, {%4,%5,%6,%7}, {%8,%9}, {%0,%1,%2,%3};\n"
        : "+f"(c[0]), "+f"(c[1]), "+f"(c[2]), "+f"(c[3])
        : "r"(a[0]), "r"(a[1]), "r"(a[2]), "r"(a[3]), "r"(b[0]), "r"(b[1]));
}

__global__ __launch_bounds__(256, 1) void gemm_mma(
    int M, int N,
    const __nv_bfloat16* __restrict__ Ah, const __nv_bfloat16* __restrict__ Al,
    const __nv_bfloat16* __restrict__ Bh, const __nv_bfloat16* __restrict__ Bl,
    float* __restrict__ Cf,
    __nv_bfloat16* __restrict__ Ch, __nv_bfloat16* __restrict__ Cl,
    const float* __restrict__ bias0, const float* __restrict__ bias1) {
    extern __shared__ __nv_bfloat16 sm[];
    __nv_bfloat16* sAh = sm;
    __nv_bfloat16* sAl = sm + 2 * A_ELE;
    __nv_bfloat16* sBh = sm + 4 * A_ELE;
    __nv_bfloat16* sBl = sm + 4 * A_ELE + 2 * B_ELE;

    const int tid  = threadIdx.x;
    const int wid  = tid >> 5, lane = tid & 31;
    const int bm = blockIdx.y * 128, bn = blockIdx.x * 64;
    const int wm = (wid >> 1) * 32, wn = (wid & 1) * 32;

    const int ar = tid >> 1;
    const int as0 = (tid & 1);
    const int br = tid >> 2;
    const int bs = (tid & 3);

    const int arow = bm + ar;
    const bool aok = arow < M;
    const uint4 z4 = make_uint4(0, 0, 0, 0);

    float acc[2][4][4] = {};
    uint4 rah0, rah1, ral0, ral1, rbh, rbl;

    auto gload = [&](int c) {
        const uint4* pah = reinterpret_cast<const uint4*>(Ah + (size_t)arow * GK + c * CH);
        const uint4* pal = reinterpret_cast<const uint4*>(Al + (size_t)arow * GK + c * CH);
        rah0 = aok ? pah[as0]     : z4;
        rah1 = aok ? pah[as0 + 2] : z4;
        ral0 = aok ? pal[as0]     : z4;
        ral1 = aok ? pal[as0 + 2] : z4;
        const uint4* pbh = reinterpret_cast<const uint4*>(Bh + (size_t)(bn + br) * GK + c * CH);
        const uint4* pbl = reinterpret_cast<const uint4*>(Bl + (size_t)(bn + br) * GK + c * CH);
        rbh = pbh[bs];
        rbl = pbl[bs];
    };
    auto sstore = [&](int buf) {
        __nv_bfloat16* dAh = sAh + buf * A_ELE + ar * AST;
        __nv_bfloat16* dAl = sAl + buf * A_ELE + ar * AST;
        *reinterpret_cast<uint4*>(dAh + as0 * 8)       = rah0;
        *reinterpret_cast<uint4*>(dAh + (as0 + 2) * 8) = rah1;
        *reinterpret_cast<uint4*>(dAl + as0 * 8)       = ral0;
        *reinterpret_cast<uint4*>(dAl + (as0 + 2) * 8) = ral1;
        *reinterpret_cast<uint4*>(sBh + buf * B_ELE + br * BST + bs * 8) = rbh;
        *reinterpret_cast<uint4*>(sBl + buf * B_ELE + br * BST + bs * 8) = rbl;
    };

    gload(0);
    sstore(0);
    __syncthreads();

    const int g   = lane >> 2;
    const int kq  = (lane & 3) * 2;

    for (int c = 0; c < GK / CH; c++) {
        const int buf = c & 1;
        if (c + 1 < GK / CH) gload(c + 1);

        const __nv_bfloat16* bAh = sAh + buf * A_ELE;
        const __nv_bfloat16* bAl = sAl + buf * A_ELE;
        const __nv_bfloat16* bBh = sBh + buf * B_ELE;
        const __nv_bfloat16* bBl = sBl + buf * B_ELE;
#pragma unroll
        for (int ks = 0; ks < 2; ks++) {
            const int k0 = ks * 16 + kq;
            uint32_t fah[2][4], fal[2][4], fbh[4][2], fbl[4][2];
#pragma unroll
            for (int mt = 0; mt < 2; mt++) {
                const int r0 = wm + mt * 16 + g;
                fah[mt][0] = *reinterpret_cast<const uint32_t*>(bAh + r0 * AST + k0);
                fah[mt][1] = *reinterpret_cast<const uint32_t*>(bAh + (r0 + 8) * AST + k0);
                fah[mt][2] = *reinterpret_cast<const uint32_t*>(bAh + r0 * AST + k0 + 8);
                fah[mt][3] = *reinterpret_cast<const uint32_t*>(bAh + (r0 + 8) * AST + k0 + 8);
                fal[mt][0] = *reinterpret_cast<const uint32_t*>(bAl + r0 * AST + k0);
                fal[mt][1] = *reinterpret_cast<const uint32_t*>(bAl + (r0 + 8) * AST + k0);
                fal[mt][2] = *reinterpret_cast<const uint32_t*>(bAl + r0 * AST + k0 + 8);
                fal[mt][3] = *reinterpret_cast<const uint32_t*>(bAl + (r0 + 8) * AST + k0 + 8);
            }
#pragma unroll
            for (int nt = 0; nt < 4; nt++) {
                const int cn = wn + nt * 8 + g;
                fbh[nt][0] = *reinterpret_cast<const uint32_t*>(bBh + cn * BST + k0);
                fbh[nt][1] = *reinterpret_cast<const uint32_t*>(bBh + cn * BST + k0 + 8);
                fbl[nt][0] = *reinterpret_cast<const uint32_t*>(bBl + cn * BST + k0);
                fbl[nt][1] = *reinterpret_cast<const uint32_t*>(bBl + cn * BST + k0 + 8);
            }
#pragma unroll
            for (int mt = 0; mt < 2; mt++)
#pragma unroll
                for (int nt = 0; nt < 4; nt++) {
                    mma16816(acc[mt][nt], fah[mt], fbh[nt]);
                    mma16816(acc[mt][nt], fah[mt], fbl[nt]);
                    mma16816(acc[mt][nt], fal[mt], fbh[nt]);
                }
        }
        if (c + 1 < GK / CH) sstore(buf ^ 1);
        __syncthreads();
    }

#pragma unroll
    for (int mt = 0; mt < 2; mt++) {
        const int r0 = bm + wm + mt * 16 + g;
#pragma unroll
        for (int nt = 0; nt < 4; nt++) {
            const int c0 = bn + wn + nt * 8 + kq;
#pragma unroll
            for (int half = 0; half < 2; half++) {
                const int row = r0 + half * 8;
                if (row < M) {
                    float v0 = acc[mt][nt][half * 2 + 0];
                    float v1 = acc[mt][nt][half * 2 + 1];
                    if (bias0) { v0 += bias0[c0]; v1 += bias0[c0 + 1]; }
                    if (bias1) { v0 += bias1[c0]; v1 += bias1[c0 + 1]; }
                    size_t o = (size_t)row * N + c0;
                    if (Ch) {
                        split_store(v0, Ch, Cl, o);
                        split_store(v1, Ch, Cl, o + 1);
                    } else {
                        Cf[o] = v0;
                        Cf[o + 1] = v1;
                    }
                }
            }
        }
    }
}

// ---------------------------------------------------------------------------
// K5: epilogue. Tile = 16 m x 16 bt, pb tile in SMEM (48KB) -> multi-CTA/SM.
// out[bt,m,o] = vp*(cx*A[bt,o] + cy*B[bt,o] - C[bt,o]) + pb[m,o]
// grid (16,16) = 256 CTAs; 192 threads, thread owns o = tid*4.
// Streaming stores (__stcs) keep the 201MB output out of L2.
// smem = 16*768*4 + 256*16 = 53248 B
// ---------------------------------------------------------------------------
#define EP_SMEM (16 * DOUT * 4 + 256 * 16)

__global__ __launch_bounds__(192, 4) void epilogue_kernel(
    const float* __restrict__ coord,
    const float* __restrict__ vism,
    float* __restrict__ out) {
    extern __shared__ float smf[];
    float4* pbs = reinterpret_cast<float4*>(smf);                   // [16][192] float4
    float4* cc  = reinterpret_cast<float4*>(smf + 16 * DOUT);       // [16*16] (cx,cy,vp,_)
    const int m0  = blockIdx.x * 16;
    const int bt0 = blockIdx.y * 16;
    const int tid = threadIdx.x;

    const float4* pb4 = reinterpret_cast<const float4*>(g_pb);
    for (int i = tid; i < 16 * 192; i += 192) {
        int r = i / 192, cf = i % 192;
        pbs[i] = pb4[(size_t)(m0 + r) * 192 + cf];
    }
    for (int e = tid; e < 256; e += 192) {
        int btl = e >> 4, ml = e & 15;
        int bt = bt0 + btl, m = m0 + ml;
        int b = bt >> 6, t = bt & 63;
        int ci = (b * Msz + m) * Tsz + t;
        float cx = coord[2 * ci + 0];
        float cy = coord[2 * ci + 1];
        float v  = vism[ci];
        float cxp = isnan(cx) ? 0.f : cx;
        float cyp = isnan(cy) ? 0.f : cy;
        float vp  = isnan(cx) ? 0.f : v;
        cc[e] = make_float4(cxp, cyp, vp, 0.f);
    }
    __syncthreads();

    const int o = tid * 4;
    for (int btl = 0; btl < 16; btl++) {
        const int bt = bt0 + btl;
        const float4 A4 = *reinterpret_cast<const float4*>(&g_ABC[(size_t)(bt * 3 + 0) * DOUT + o]);
        const float4 B4 = *reinterpret_cast<const float4*>(&g_ABC[(size_t)(bt * 3 + 1) * DOUT + o]);
        const float4 C4 = *reinterpret_cast<const float4*>(&g_ABC[(size_t)(bt * 3 + 2) * DOUT + o]);
        float* obase = out + ((size_t)bt * Msz + m0) * DOUT + o;
#pragma unroll 4
        for (int ml = 0; ml < 16; ml++) {
            float4 k = cc[btl * 16 + ml];
            float4 p = pbs[ml * 192 + tid];
            float4 r;
            r.x = k.z * (k.x * A4.x + k.y * B4.x - C4.x) + p.x;
            r.y = k.z * (k.x * A4.y + k.y * B4.y - C4.y) + p.y;
            r.z = k.z * (k.x * A4.z + k.y * B4.z - C4.z) + p.z;
            r.w = k.z * (k.x * A4.w + k.y * B4.w - C4.w) + p.w;
            __stcs(reinterpret_cast<float4*>(obase + (size_t)ml * DOUT), r);
        }
    }
}

// ---------------------------------------------------------------------------
extern "C" void kernel_launch(void* const* d_in, const int* in_sizes, int n_in,
                              void* d_out, int out_size) {
    const float* coord = (const float*)d_in[0];
    const float* vism  = (const float*)d_in[1];
    const float* pos   = (const float*)d_in[2];
    const float* fc1w  = (const float*)d_in[3];
    const float* fc1b  = (const float*)d_in[4];
    const float* fow   = (const float*)d_in[5];
    const float* fob   = (const float*)d_in[6];
    float* out = (float*)d_out;

    __nv_bfloat16 *Ubh, *Ubl, *Wsh, *Wsl, *W1h, *W1l, *W2h, *W2l, *W3h, *W3l, *psh, *psl;
    float *ABC, *pb;
    cudaGetSymbolAddress((void**)&Ubh, g_Ub_h); cudaGetSymbolAddress((void**)&Ubl, g_Ub_l);
    cudaGetSymbolAddress((void**)&Wsh, g_Ws_h); cudaGetSymbolAddress((void**)&Wsl, g_Ws_l);
    cudaGetSymbolAddress((void**)&W1h, g_W1_h); cudaGetSymbolAddress((void**)&W1l, g_W1_l);
    cudaGetSymbolAddress((void**)&W2h, g_W2_h); cudaGetSymbolAddress((void**)&W2l, g_W2_l);
    cudaGetSymbolAddress((void**)&W3h, g_W3_h); cudaGetSymbolAddress((void**)&W3l, g_W3_l);
    cudaGetSymbolAddress((void**)&psh, g_ps_h); cudaGetSymbolAddress((void**)&psl, g_ps_l);
    cudaGetSymbolAddress((void**)&ABC, g_ABC);  cudaGetSymbolAddress((void**)&pb,  g_pb);

    cudaFuncSetAttribute(gemm_mma, cudaFuncAttributeMaxDynamicSharedMemorySize, GEMM_SMEM);
    cudaFuncSetAttribute(epilogue_kernel, cudaFuncAttributeMaxDynamicSharedMemorySize, EP_SMEM);

    // prep: masked u-vectors, pos split, weight transposes+splits
    build_u_kernel<<<BT * Msz / 256, 256>>>(coord, vism, fc1b);
    split_kernel<<<(Msz * GK) / 256, 256>>>(pos, psh, psl, Msz * GK);
    transpose_split<<<dim3(512 / 32, GK / 32), dim3(32, 8)>>>(fc1w, 512, GK, W1h, W1l);
    transpose_split<<<dim3(DOUT / 32, GK / 32), dim3(32, 8)>>>(fow, DOUT, GK, W2h, W2l);
    transpose_split<<<dim3(DOUT / 32, GK / 32), dim3(32, 8)>>>(fow + (size_t)512 * DOUT, DOUT, GK, W3h, W3l);

    // GEMM1: Wstack[0..767] = Ub(768x512) @ fc1_w  -> bf16 split out
    gemm_mma<<<dim3(DMOT / 64, 6), 256, GEMM_SMEM>>>(768, DMOT, Ubh, Ubl, W1h, W1l,
                                                     nullptr, Wsh, Wsl, nullptr, nullptr);
    // GEMM2: ABC(769x768) = Wstack(769x512) @ fow_top -> fp32
    gemm_mma<<<dim3(DOUT / 64, 7), 256, GEMM_SMEM>>>(769, DOUT, Wsh, Wsl, W2h, W2l,
                                                     ABC, nullptr, nullptr, nullptr, nullptr);
    // GEMM3: pb(256x768) = pos @ fow_bot + fob + Bias1(ABC row 768) -> fp32
    gemm_mma<<<dim3(DOUT / 64, 2), 256, GEMM_SMEM>>>(Msz, DOUT, psh, psl, W3h, W3l,
                                                     pb, nullptr, nullptr, fob, ABC + (size_t)768 * DOUT);

    // epilogue: stream 201MB output
    epilogue_kernel<<<dim3(Msz / 16, BT / 16), 192, EP_SMEM>>>(coord, vism, out);
}

// round 6
// speedup vs baseline: 2.5046x; 1.2842x over previous
#include <cuda_runtime.h>
#include <cuda_bf16.h>
#include <cstdint>
#include <math.h>

#define Bsz  4
#define Msz  256
#define Tsz  64
#define BT   256          // B*T
#define DMOT 512
#define DOUT 768
#define GK   512          // K dim of all GEMMs

// ---------------------------------------------------------------------------
// Scratch (__device__ globals — allocation-free rule)
// ---------------------------------------------------------------------------
__device__ __nv_bfloat16 g_Ub_h[768 * GK], g_Ub_l[768 * GK];      // A of GEMM1
__device__ __nv_bfloat16 g_Ws_h[769 * GK], g_Ws_l[769 * GK];      // GEMM1 out + fc1_b row
__device__ __nv_bfloat16 g_W1_h[512 * GK], g_W1_l[512 * GK];      // fc1_w^T   [512n][512k]
__device__ __nv_bfloat16 g_W2_h[768 * GK], g_W2_l[768 * GK];      // fow_top^T [768n][512k]
__device__ __nv_bfloat16 g_W3_h[768 * GK], g_W3_l[768 * GK];      // fow_bot^T [768n][512k]
__device__ __nv_bfloat16 g_ps_h[256 * GK], g_ps_l[256 * GK];      // pos split
__device__ float g_ABC[769 * DOUT];                               // A,B,C rows + Bias1 row 768
__device__ float g_pb[Msz * DOUT];                                // pos@Wbot + fob (Bias1 added in epilogue)

__device__ __forceinline__ void split_store(float v, __nv_bfloat16* h, __nv_bfloat16* l, size_t o) {
    __nv_bfloat16 hh = __float2bfloat16(v);
    h[o] = hh;
    l[o] = __float2bfloat16(v - __bfloat162float(hh));
}

// ---------------------------------------------------------------------------
// K1 (fused prep): block-partitioned — 3 weight transposes+splits, build_u, pos split
//   blocks [0,256):      W1 transpose  (16 n-tiles x 16 k-tiles)
//   blocks [256,640):    W2 transpose  (24 x 16)
//   blocks [640,1024):   W3 transpose  (24 x 16)
//   blocks [1024,1280):  build_u (+ fc1_b row)
//   blocks [1280,1792):  pos split
// ---------------------------------------------------------------------------
__device__ __forceinline__ void transpose_tile(const float* __restrict__ W, int ldw,
                                               int n0, int k0,
                                               __nv_bfloat16* __restrict__ Th,
                                               __nv_bfloat16* __restrict__ Tl,
                                               float* t /* [32][33] smem */) {
    int tx = threadIdx.x & 31, ty = threadIdx.x >> 5;
#pragma unroll
    for (int i = 0; i < 4; i++)
        t[(ty + i * 8) * 33 + tx] = W[(size_t)(k0 + ty + i * 8) * ldw + n0 + tx];
    __syncthreads();
#pragma unroll
    for (int i = 0; i < 4; i++) {
        float v = t[tx * 33 + ty + i * 8];
        split_store(v, Th, Tl, (size_t)(n0 + ty + i * 8) * GK + k0 + tx);
    }
}

__global__ __launch_bounds__(256) void prep_kernel(
    const float* __restrict__ coord, const float* __restrict__ vism,
    const float* __restrict__ pos,   const float* __restrict__ fc1w,
    const float* __restrict__ fc1b,  const float* __restrict__ fow) {
    __shared__ float t[32 * 33];
    const int b = blockIdx.x;
    const int tid = threadIdx.x;

    if (b < 256) {                       // W1: 512x512
        transpose_tile(fc1w, 512, (b & 15) * 32, (b >> 4) * 32, g_W1_h, g_W1_l, t);
    } else if (b < 640) {                // W2: fow rows [0,512)
        int i = b - 256;
        transpose_tile(fow, DOUT, (i % 24) * 32, (i / 24) * 32, g_W2_h, g_W2_l, t);
    } else if (b < 1024) {               // W3: fow rows [512,1024)
        int i = b - 640;
        transpose_tile(fow + (size_t)512 * DOUT, DOUT, (i % 24) * 32, (i / 24) * 32, g_W3_h, g_W3_l, t);
    } else if (b < 1280) {               // build_u
        int idx = (b - 1024) * 256 + tid;
        {
            int n  = idx & (Msz - 1);
            int bt = idx >> 8;
            int bb = bt >> 6;
            int tt = bt & (Tsz - 1);
            int ci = (bb * Msz + n) * Tsz + tt;
            float cx = coord[2 * ci + 0];
            float cy = coord[2 * ci + 1];
            float v  = vism[ci];
            float cxp = isnan(cx) ? 0.f : cx;
            float cyp = isnan(cy) ? 0.f : cy;
            float vp  = isnan(cx) ? 0.f : v;
            size_t r0 = (size_t)bt * 3 * GK;
            __nv_bfloat16 z = __float2bfloat16(0.f);
            split_store(vp, g_Ub_h, g_Ub_l, r0 + 2 * n);
            g_Ub_h[r0 + 2 * n + 1] = z;  g_Ub_l[r0 + 2 * n + 1] = z;
            g_Ub_h[r0 + GK + 2 * n] = z; g_Ub_l[r0 + GK + 2 * n] = z;
            split_store(vp,       g_Ub_h, g_Ub_l, r0 + GK + 2 * n + 1);
            split_store(vp * cxp, g_Ub_h, g_Ub_l, r0 + 2 * GK + 2 * n);
            split_store(vp * cyp, g_Ub_h, g_Ub_l, r0 + 2 * GK + 2 * n + 1);
        }
        if (idx < DMOT) split_store(fc1b[idx], g_Ws_h, g_Ws_l, (size_t)768 * GK + idx);
    } else {                             // pos split
        int idx = (b - 1280) * 256 + tid;
        split_store(pos[idx], g_ps_h, g_ps_l, idx);
    }
}

// ---------------------------------------------------------------------------
// GEMM core: bf16 mma.sync, 3-term hi/lo split. CTA 128(M) x 64(N), 256 thr.
// ---------------------------------------------------------------------------
#define CH   32
#define AST  40
#define BST  40
#define A_ELE (128 * AST)
#define B_ELE (64 * BST)
#define GEMM_SMEM ((2 * A_ELE * 2 + 2 * B_ELE * 2) * 2)  // 61440 bytes

__device__ __forceinline__ void mma16816(float* c, const uint32_t* a, const uint32_t* b) {
    asm volatile(
        "mma.sync.aligned.m16n8k16.row.col.f32.bf16.bf16.f32 "
        "{%0,%1,%2,%3}, {%4,%5,%6,%7}, {%8,%9}, {%0,%1,%2,%3};\n"
        : "+f"(c[0]), "+f"(c[1]), "+f"(c[2]), "+f"(c[3])
        : "r"(a[0]), "r"(a[1]), "r"(a[2]), "r"(a[3]), "r"(b[0]), "r"(b[1]));
}

__device__ void gemm_core(
    int M, int N, int bm, int bn,
    const __nv_bfloat16* __restrict__ Ah, const __nv_bfloat16* __restrict__ Al,
    const __nv_bfloat16* __restrict__ Bh, const __nv_bfloat16* __restrict__ Bl,
    float* __restrict__ Cf,
    __nv_bfloat16* __restrict__ Ch, __nv_bfloat16* __restrict__ Cl,
    const float* __restrict__ bias0,
    __nv_bfloat16* sm) {
    __nv_bfloat16* sAh = sm;
    __nv_bfloat16* sAl = sm + 2 * A_ELE;
    __nv_bfloat16* sBh = sm + 4 * A_ELE;
    __nv_bfloat16* sBl = sm + 4 * A_ELE + 2 * B_ELE;

    const int tid  = threadIdx.x;
    const int wid  = tid >> 5, lane = tid & 31;
    const int wm = (wid >> 1) * 32, wn = (wid & 1) * 32;

    const int ar = tid >> 1;
    const int as0 = (tid & 1);
    const int br = tid >> 2;
    const int bs = (tid & 3);

    const int arow = bm + ar;
    const bool aok = arow < M;
    const uint4 z4 = make_uint4(0, 0, 0, 0);

    float acc[2][4][4] = {};
    uint4 rah0, rah1, ral0, ral1, rbh, rbl;

    auto gload = [&](int c) {
        const uint4* pah = reinterpret_cast<const uint4*>(Ah + (size_t)arow * GK + c * CH);
        const uint4* pal = reinterpret_cast<const uint4*>(Al + (size_t)arow * GK + c * CH);
        rah0 = aok ? pah[as0]     : z4;
        rah1 = aok ? pah[as0 + 2] : z4;
        ral0 = aok ? pal[as0]     : z4;
        ral1 = aok ? pal[as0 + 2] : z4;
        const uint4* pbh = reinterpret_cast<const uint4*>(Bh + (size_t)(bn + br) * GK + c * CH);
        const uint4* pbl = reinterpret_cast<const uint4*>(Bl + (size_t)(bn + br) * GK + c * CH);
        rbh = pbh[bs];
        rbl = pbl[bs];
    };
    auto sstore = [&](int buf) {
        __nv_bfloat16* dAh = sAh + buf * A_ELE + ar * AST;
        __nv_bfloat16* dAl = sAl + buf * A_ELE + ar * AST;
        *reinterpret_cast<uint4*>(dAh + as0 * 8)       = rah0;
        *reinterpret_cast<uint4*>(dAh + (as0 + 2) * 8) = rah1;
        *reinterpret_cast<uint4*>(dAl + as0 * 8)       = ral0;
        *reinterpret_cast<uint4*>(dAl + (as0 + 2) * 8) = ral1;
        *reinterpret_cast<uint4*>(sBh + buf * B_ELE + br * BST + bs * 8) = rbh;
        *reinterpret_cast<uint4*>(sBl + buf * B_ELE + br * BST + bs * 8) = rbl;
    };

    gload(0);
    sstore(0);
    __syncthreads();

    const int g   = lane >> 2;
    const int kq  = (lane & 3) * 2;

    for (int c = 0; c < GK / CH; c++) {
        const int buf = c & 1;
        if (c + 1 < GK / CH) gload(c + 1);

        const __nv_bfloat16* bAh = sAh + buf * A_ELE;
        const __nv_bfloat16* bAl = sAl + buf * A_ELE;
        const __nv_bfloat16* bBh = sBh + buf * B_ELE;
        const __nv_bfloat16* bBl = sBl + buf * B_ELE;
#pragma unroll
        for (int ks = 0; ks < 2; ks++) {
            const int k0 = ks * 16 + kq;
            uint32_t fah[2][4], fal[2][4], fbh[4][2], fbl[4][2];
#pragma unroll
            for (int mt = 0; mt < 2; mt++) {
                const int r0 = wm + mt * 16 + g;
                fah[mt][0] = *reinterpret_cast<const uint32_t*>(bAh + r0 * AST + k0);
                fah[mt][1] = *reinterpret_cast<const uint32_t*>(bAh + (r0 + 8) * AST + k0);
                fah[mt][2] = *reinterpret_cast<const uint32_t*>(bAh + r0 * AST + k0 + 8);
                fah[mt][3] = *reinterpret_cast<const uint32_t*>(bAh + (r0 + 8) * AST + k0 + 8);
                fal[mt][0] = *reinterpret_cast<const uint32_t*>(bAl + r0 * AST + k0);
                fal[mt][1] = *reinterpret_cast<const uint32_t*>(bAl + (r0 + 8) * AST + k0);
                fal[mt][2] = *reinterpret_cast<const uint32_t*>(bAl + r0 * AST + k0 + 8);
                fal[mt][3] = *reinterpret_cast<const uint32_t*>(bAl + (r0 + 8) * AST + k0 + 8);
            }
#pragma unroll
            for (int nt = 0; nt < 4; nt++) {
                const int cn = wn + nt * 8 + g;
                fbh[nt][0] = *reinterpret_cast<const uint32_t*>(bBh + cn * BST + k0);
                fbh[nt][1] = *reinterpret_cast<const uint32_t*>(bBh + cn * BST + k0 + 8);
                fbl[nt][0] = *reinterpret_cast<const uint32_t*>(bBl + cn * BST + k0);
                fbl[nt][1] = *reinterpret_cast<const uint32_t*>(bBl + cn * BST + k0 + 8);
            }
#pragma unroll
            for (int mt = 0; mt < 2; mt++)
#pragma unroll
                for (int nt = 0; nt < 4; nt++) {
                    mma16816(acc[mt][nt], fah[mt], fbh[nt]);
                    mma16816(acc[mt][nt], fah[mt], fbl[nt]);
                    mma16816(acc[mt][nt], fal[mt], fbh[nt]);
                }
        }
        if (c + 1 < GK / CH) sstore(buf ^ 1);
        __syncthreads();
    }

#pragma unroll
    for (int mt = 0; mt < 2; mt++) {
        const int r0 = bm + wm + mt * 16 + g;
#pragma unroll
        for (int nt = 0; nt < 4; nt++) {
            const int c0 = bn + wn + nt * 8 + kq;
#pragma unroll
            for (int half = 0; half < 2; half++) {
                const int row = r0 + half * 8;
                if (row < M) {
                    float v0 = acc[mt][nt][half * 2 + 0];
                    float v1 = acc[mt][nt][half * 2 + 1];
                    if (bias0) { v0 += bias0[c0]; v1 += bias0[c0 + 1]; }
                    size_t o = (size_t)row * N + c0;
                    if (Ch) {
                        split_store(v0, Ch, Cl, o);
                        split_store(v1, Ch, Cl, o + 1);
                    } else {
                        Cf[o] = v0;
                        Cf[o + 1] = v1;
                    }
                }
            }
        }
    }
}

// ---------------------------------------------------------------------------
// K2: GEMM1 (Ws = Ub @ W1, split out) and GEMM3 (pb = pos @ W3 + fob) fused.
// grid (12,6,2): z=0 -> GEMM1 (8x6 tiles), z=1 -> GEMM3 (12x2 tiles).
// ---------------------------------------------------------------------------
__global__ __launch_bounds__(256, 1) void gemm13_kernel(const float* __restrict__ fob) {
    extern __shared__ __nv_bfloat16 sm[];
    if (blockIdx.z == 0) {
        if (blockIdx.x >= 8) return;
        gemm_core(768, DMOT, blockIdx.y * 128, blockIdx.x * 64,
                  g_Ub_h, g_Ub_l, g_W1_h, g_W1_l,
                  nullptr, g_Ws_h, g_Ws_l, nullptr, sm);
    } else {
        if (blockIdx.y >= 2) return;
        gemm_core(Msz, DOUT, blockIdx.y * 128, blockIdx.x * 64,
                  g_ps_h, g_ps_l, g_W3_h, g_W3_l,
                  g_pb, nullptr, nullptr, fob, sm);
    }
}

// K3: GEMM2 (ABC = Ws @ W2), grid (12,7)
__global__ __launch_bounds__(256, 1) void gemm2_kernel() {
    extern __shared__ __nv_bfloat16 sm[];
    gemm_core(769, DOUT, blockIdx.y * 128, blockIdx.x * 64,
              g_Ws_h, g_Ws_l, g_W2_h, g_W2_l,
              g_ABC, nullptr, nullptr, nullptr, sm);
}

// ---------------------------------------------------------------------------
// K4: epilogue. Tile = 16 m x 16 bt; pb tile (+Bias1 from ABC row 768) in SMEM.
// out[bt,m,o] = vp*(cx*A[bt,o] + cy*B[bt,o] - C[bt,o]) + pb[m,o] + Bias1[o]
// ---------------------------------------------------------------------------
#define EP_SMEM (16 * DOUT * 4 + 256 * 16)

__global__ __launch_bounds__(192, 4) void epilogue_kernel(
    const float* __restrict__ coord,
    const float* __restrict__ vism,
    float* __restrict__ out) {
    extern __shared__ float smf[];
    float4* pbs = reinterpret_cast<float4*>(smf);                   // [16][192] float4
    float4* cc  = reinterpret_cast<float4*>(smf + 16 * DOUT);       // [16*16] (cx,cy,vp,_)
    const int m0  = blockIdx.x * 16;
    const int bt0 = blockIdx.y * 16;
    const int tid = threadIdx.x;

    const float4* pb4 = reinterpret_cast<const float4*>(g_pb);
    const float4* b14 = reinterpret_cast<const float4*>(g_ABC + (size_t)768 * DOUT);
    for (int i = tid; i < 16 * 192; i += 192) {
        int r = i / 192, cf = i % 192;
        float4 p = pb4[(size_t)(m0 + r) * 192 + cf];
        float4 bb = b14[cf];
        p.x += bb.x; p.y += bb.y; p.z += bb.z; p.w += bb.w;
        pbs[i] = p;
    }
    for (int e = tid; e < 256; e += 192) {
        int btl = e >> 4, ml = e & 15;
        int bt = bt0 + btl, m = m0 + ml;
        int b = bt >> 6, t = bt & 63;
        int ci = (b * Msz + m) * Tsz + t;
        float cx = coord[2 * ci + 0];
        float cy = coord[2 * ci + 1];
        float v  = vism[ci];
        float cxp = isnan(cx) ? 0.f : cx;
        float cyp = isnan(cy) ? 0.f : cy;
        float vp  = isnan(cx) ? 0.f : v;
        cc[e] = make_float4(cxp, cyp, vp, 0.f);
    }
    __syncthreads();

    const int o = tid * 4;
    for (int btl = 0; btl < 16; btl++) {
        const int bt = bt0 + btl;
        const float4 A4 = *reinterpret_cast<const float4*>(&g_ABC[(size_t)(bt * 3 + 0) * DOUT + o]);
        const float4 B4 = *reinterpret_cast<const float4*>(&g_ABC[(size_t)(bt * 3 + 1) * DOUT + o]);
        const float4 C4 = *reinterpret_cast<const float4*>(&g_ABC[(size_t)(bt * 3 + 2) * DOUT + o]);
        float* obase = out + ((size_t)bt * Msz + m0) * DOUT + o;
#pragma unroll 4
        for (int ml = 0; ml < 16; ml++) {
            float4 k = cc[btl * 16 + ml];
            float4 p = pbs[ml * 192 + tid];
            float4 r;
            r.x = k.z * (k.x * A4.x + k.y * B4.x - C4.x) + p.x;
            r.y = k.z * (k.x * A4.y + k.y * B4.y - C4.y) + p.y;
            r.z = k.z * (k.x * A4.z + k.y * B4.z - C4.z) + p.z;
            r.w = k.z * (k.x * A4.w + k.y * B4.w - C4.w) + p.w;
            __stcs(reinterpret_cast<float4*>(obase + (size_t)ml * DOUT), r);
        }
    }
}

// ---------------------------------------------------------------------------
extern "C" void kernel_launch(void* const* d_in, const int* in_sizes, int n_in,
                              void* d_out, int out_size) {
    const float* coord = (const float*)d_in[0];
    const float* vism  = (const float*)d_in[1];
    const float* pos   = (const float*)d_in[2];
    const float* fc1w  = (const float*)d_in[3];
    const float* fc1b  = (const float*)d_in[4];
    const float* fow   = (const float*)d_in[5];
    const float* fob   = (const float*)d_in[6];
    float* out = (float*)d_out;

    cudaFuncSetAttribute(gemm13_kernel, cudaFuncAttributeMaxDynamicSharedMemorySize, GEMM_SMEM);
    cudaFuncSetAttribute(gemm2_kernel,  cudaFuncAttributeMaxDynamicSharedMemorySize, GEMM_SMEM);
    cudaFuncSetAttribute(epilogue_kernel, cudaFuncAttributeMaxDynamicSharedMemorySize, EP_SMEM);

    // K1: fused prep (transposes+splits, build_u, pos split)
    prep_kernel<<<1792, 256>>>(coord, vism, pos, fc1w, fc1b, fow);

    // K2: GEMM1 + GEMM3 fused
    gemm13_kernel<<<dim3(12, 6, 2), 256, GEMM_SMEM>>>(fob);

    // K3: GEMM2
    gemm2_kernel<<<dim3(12, 7), 256, GEMM_SMEM>>>();

    // K4: epilogue — stream 201MB output
    epilogue_kernel<<<dim3(Msz / 16, BT / 16), 192, EP_SMEM>>>(coord, vism, out);
}